// round 1
// baseline (speedup 1.0000x reference)
#include <cuda_runtime.h>

// ARIMA(16,1,16) over S=2^20 diffed samples.
// Phase A: x[t] = y[t] - AR(y)  (parallel, memory-bound)
// Phase B: err[t] = x[t] - sum_j c_j err[t-j]  (order-16 IIR) via overlapped
//          chunks: each thread runs W warmup steps (zero init state; error
//          decays geometrically since the filter is stable) then L real steps,
//          accumulating sum(err^2).
// Phase C: out = acc / S

#define S_LEN   1048576      // 2^20 = (1048577 - 1) after D=1 differencing
#define CHUNK_L 64
#define NCHUNK  (S_LEN / CHUNK_L)   // 16384
#define WARM    1024

__device__ float  g_x[S_LEN];
__device__ double g_acc;

// ---------------- Phase A: compute x[t] ----------------
__global__ void prep_kernel(const float* __restrict__ s,
                            const float* __restrict__ w_ar) {
    __shared__ float sy[272];                 // y[bstart-16 .. bstart+255]
    const int bstart = blockIdx.x * 256;
    for (int i = threadIdx.x; i < 272; i += 256) {
        int gi = bstart - 16 + i;
        float yv = 0.f;
        if (gi >= 0 && gi < S_LEN) yv = s[gi + 1] - s[gi];
        sy[i] = yv;
    }
    __syncthreads();

    const int t = bstart + threadIdx.x;       // t < S_LEN always (4096*256)
    float yt = sy[threadIdx.x + 16];
    float ar = 0.f;
#pragma unroll
    for (int k = 0; k < 16; ++k)
        ar = fmaf(w_ar[k], sy[threadIdx.x + k], ar);   // y[t-16+k]
    g_x[t] = (t > 16) ? (yt - ar) : yt;       // pred only applies for t > 16
    if (t == 0) g_acc = 0.0;
}

// ---------------- Phase B: chunked IIR ----------------
// Transposed direct-form II: err = x + d[0];
//   d[j] = d[j+1] + nc[j]*err (j<15), d[15] = nc[15]*err
// where nc[j] = -c_{j+1} = -w_ma[15-j].
__global__ void __launch_bounds__(128) iir_kernel(const float* __restrict__ w_ma) {
    const int cid = blockIdx.x * blockDim.x + threadIdx.x;   // chunk id

    float nc[16];
#pragma unroll
    for (int j = 0; j < 16; ++j) nc[j] = -w_ma[15 - j];

    float d[16];
#pragma unroll
    for (int j = 0; j < 16; ++j) d[j] = 0.f;

    const int cs = cid * CHUNK_L;
    const int ce = cs + CHUNK_L;
    float acc = 0.f;

    if (cid == 0) {
        // exact: t<=16 has pred=0 (err = x = y)
        for (int t = 0; t < CHUNK_L; ++t) {
            float x   = g_x[t];
            float err = (t > 16) ? (x + d[0]) : x;
#pragma unroll
            for (int j = 0; j < 15; ++j) d[j] = fmaf(nc[j], err, d[j + 1]);
            d[15] = nc[15] * err;
            acc = fmaf(err, err, acc);
        }
    } else {
        int t = cs - WARM;
        if (t < 17) {
            // exact prologue from t=0 (these chunks end up exact, not approx)
            for (t = 0; t < 17; ++t) {
                float err = g_x[t];               // pred = 0 here
#pragma unroll
                for (int j = 0; j < 15; ++j) d[j] = fmaf(nc[j], err, d[j + 1]);
                d[15] = nc[15] * err;
            }
        }
        // warmup: run recurrence, discard outputs
#pragma unroll 4
        for (; t < cs; ++t) {
            float x   = g_x[t];
            float err = x + d[0];
#pragma unroll
            for (int j = 0; j < 15; ++j) d[j] = fmaf(nc[j], err, d[j + 1]);
            d[15] = nc[15] * err;
        }
        // main: accumulate err^2
#pragma unroll 4
        for (t = cs; t < ce; ++t) {
            float x   = g_x[t];
            float err = x + d[0];
#pragma unroll
            for (int j = 0; j < 15; ++j) d[j] = fmaf(nc[j], err, d[j + 1]);
            d[15] = nc[15] * err;
            acc = fmaf(err, err, acc);
        }
    }

    // warp reduce then one double atomic per warp
#pragma unroll
    for (int off = 16; off; off >>= 1)
        acc += __shfl_down_sync(0xffffffffu, acc, off);
    if ((threadIdx.x & 31) == 0)
        atomicAdd(&g_acc, (double)acc);
}

// ---------------- Phase C: finalize ----------------
__global__ void finish_kernel(float* __restrict__ out) {
    out[0] = (float)(g_acc * (1.0 / (double)S_LEN));
}

extern "C" void kernel_launch(void* const* d_in, const int* in_sizes, int n_in,
                              void* d_out, int out_size) {
    const float* series = (const float*)d_in[0];   // 1048577 f32
    const float* w_ar   = (const float*)d_in[1];   // 16 f32
    const float* w_ma   = (const float*)d_in[2];   // 16 f32
    float* out = (float*)d_out;

    prep_kernel<<<S_LEN / 256, 256>>>(series, w_ar);
    iir_kernel<<<NCHUNK / 128, 128>>>(w_ma);
    finish_kernel<<<1, 1>>>(out);
}

// round 2
// speedup vs baseline: 4.3415x; 4.3415x over previous
#include <cuda_runtime.h>

// ARIMA(16,1,16), S = 2^20 diffed samples.
// Phase A (prep): x[t] = y[t] - AR16(y), y = diff(series). Parallel.
// Phase B (iir):  err[t] = x[t] - sum_j c_j err[t-j], order-16 IIR via
//                 overlapped chunks (W=256 warmup, L=64 per thread).
//                 Warp-cooperative smem tile, conflict-free padded layout.
// Phase C: mean(err^2).

#define S_LEN   1048576
#define CHUNK_L 64
#define WARM    256
#define STEPS   (WARM + CHUNK_L)          // 320 = 5 * 64
#define NCHUNK  (S_LEN / CHUNK_L)         // 16384
#define TILE_F  (WARM + 32 * CHUNK_L)     // 2304 floats per warp
#define TILE_P  (TILE_F + TILE_F / 64 + 4)  // padded: 2344

__device__ float  g_x[S_LEN];
__device__ double g_acc;

// ---------------- Phase A ----------------
__global__ void __launch_bounds__(256) prep_kernel(const float* __restrict__ s,
                                                   const float* __restrict__ w_ar) {
    __shared__ float sy[1040];            // y[bstart-16 .. bstart+1023]
    const int bstart = blockIdx.x * 1024;
    for (int i = threadIdx.x; i < 1040; i += 256) {
        int g = bstart - 16 + i;          // g+1 <= S_LEN always
        sy[i] = (g >= 0) ? (s[g + 1] - s[g]) : 0.f;
    }
    __syncthreads();

    float war[16];
#pragma unroll
    for (int k = 0; k < 16; ++k) war[k] = w_ar[k];

#pragma unroll
    for (int k = 0; k < 4; ++k) {
        const int li = threadIdx.x + 256 * k;
        const int t  = bstart + li;
        float yt = sy[li + 16];
        float ar = 0.f;
#pragma unroll
        for (int j = 0; j < 16; ++j)
            ar = fmaf(war[j], sy[li + j], ar);
        g_x[t] = (t > 16) ? (yt - ar) : yt;
    }
    if (bstart == 0 && threadIdx.x == 0) g_acc = 0.0;
}

// ---------------- Phase B ----------------
// Padded smem index: f(r) = r + (r>>6). For lane l, step j:
// r = 64*l + j  ->  f = 65*l + 65*(j/64) + (j%64); banks distinct per lane.
__global__ void __launch_bounds__(128) iir_kernel(const float* __restrict__ w_ma) {
    __shared__ float tile[4][TILE_P];
    const int wid  = threadIdx.x >> 5;
    const int lane = threadIdx.x & 31;
    const int gwarp = blockIdx.x * 4 + wid;
    const int warpT0 = gwarp * (32 * CHUNK_L) - WARM;   // global t of tile[0]
    float* tw = tile[wid];

    // Cooperative coalesced tile load (warp-private; __syncwarp only).
    if (warpT0 >= 0) {
        const float4* src = (const float4*)(g_x + warpT0);  // 16B aligned
        for (int i = lane; i < TILE_F / 4; i += 32) {
            float4 v = src[i];
            int r  = i * 4;                 // r%64 in {0..60}: no group crossing
            int fr = r + (r >> 6);
            tw[fr] = v.x; tw[fr + 1] = v.y; tw[fr + 2] = v.z; tw[fr + 3] = v.w;
        }
    } else {                                // only warp 0 of block 0
        for (int i = lane; i < TILE_F; i += 32) {
            int g = warpT0 + i;
            tw[i + (i >> 6)] = (g >= 0) ? g_x[g] : 0.f;
        }
    }
    __syncwarp();

    float nc[16];
#pragma unroll
    for (int j = 0; j < 16; ++j) nc[j] = -w_ma[15 - j];
    float d[16];
#pragma unroll
    for (int j = 0; j < 16; ++j) d[j] = 0.f;
    float acc = 0.f;

    int idx = 65 * lane;                    // f(64*lane)

    if (blockIdx.x == 0) {
        // Guarded path: handles t<0 (x=0) and t<=16 (pred suppressed).
        int t = warpT0 + 64 * lane;
        for (int jo = 0; jo < 5; ++jo) {
#pragma unroll 8
            for (int ji = 0; ji < 64; ++ji) {
                float x   = tw[idx + ji];
                float e0  = x + d[0];
                float err = (t > 16) ? e0 : x;
#pragma unroll
                for (int j = 0; j < 15; ++j) d[j] = fmaf(nc[j], err, d[j + 1]);
                d[15] = nc[15] * err;
                if (jo == 4) acc = fmaf(err, err, acc);
                ++t;
            }
            idx += 65;
        }
    } else {
        // Warmup (4 x 64 steps, discard outputs)
        for (int jo = 0; jo < 4; ++jo) {
#pragma unroll 8
            for (int ji = 0; ji < 64; ++ji) {
                float err = tw[idx + ji] + d[0];
#pragma unroll
                for (int j = 0; j < 15; ++j) d[j] = fmaf(nc[j], err, d[j + 1]);
                d[15] = nc[15] * err;
            }
            idx += 65;
        }
        // Main 64 steps, accumulate err^2
#pragma unroll 8
        for (int ji = 0; ji < 64; ++ji) {
            float err = tw[idx + ji] + d[0];
#pragma unroll
            for (int j = 0; j < 15; ++j) d[j] = fmaf(nc[j], err, d[j + 1]);
            d[15] = nc[15] * err;
            acc = fmaf(err, err, acc);
        }
    }

    // Warp reduce, one double atomic per warp.
#pragma unroll
    for (int off = 16; off; off >>= 1)
        acc += __shfl_down_sync(0xffffffffu, acc, off);
    if (lane == 0) atomicAdd(&g_acc, (double)acc);
}

// ---------------- Phase C ----------------
__global__ void finish_kernel(float* __restrict__ out) {
    out[0] = (float)(g_acc * (1.0 / (double)S_LEN));
}

extern "C" void kernel_launch(void* const* d_in, const int* in_sizes, int n_in,
                              void* d_out, int out_size) {
    const float* series = (const float*)d_in[0];
    const float* w_ar   = (const float*)d_in[1];
    const float* w_ma   = (const float*)d_in[2];
    float* out = (float*)d_out;

    prep_kernel<<<S_LEN / 1024, 256>>>(series, w_ar);
    iir_kernel<<<NCHUNK / 128, 128>>>(w_ma);
    finish_kernel<<<1, 1>>>(out);
}

// round 3
// speedup vs baseline: 5.4042x; 1.2448x over previous
#include <cuda_runtime.h>

// ARIMA(16,1,16), S = 2^20 diffed samples. Single fused kernel:
//   per warp: load series segment -> 18-tap FIR (x = y - AR(y), telescoped
//   onto raw s) into smem tile -> order-16 IIR with W=128 warmup, L=64 per
//   lane -> warp partial sum. finish kernel reduces 512 partials.

#define S_LEN   1048576
#define CHUNK_L 64
#define WARM    128
#define NWARP   512
#define SPAN    2048                      // x-values per warp (32 lanes * 64)
#define TILE_F  (WARM + SPAN)             // 2176
#define TILE_P  (TILE_F + TILE_F / 64 + 2) // 2212 padded
#define SS_N    2196                      // 549 float4 (need 2193)

__device__ float g_partial[NWARP];

__global__ void __launch_bounds__(32) fused_kernel(const float* __restrict__ s,
                                                   const float* __restrict__ w_ar,
                                                   const float* __restrict__ w_ma) {
    __shared__ __align__(16) float ss[SS_N];
    __shared__ __align__(16) float xt[TILE_P];
    const int l  = threadIdx.x;
    const int g  = blockIdx.x;
    const int T0 = g * SPAN - WARM;       // global t of tile r=0
    const int sb = T0 - 16;               // ss[i] = s[sb + i]; multiple of 4

    // ---- load series segment (coalesced float4; edge warps guarded) ----
    if (g == 0 || g == NWARP - 1) {
        for (int i = l; i < SS_N; i += 32) {
            int p = sb + i;
            p = p < 0 ? 0 : (p > S_LEN ? S_LEN : p);   // s has S_LEN+1 elems
            ss[i] = s[p];
        }
    } else {
        const float4* src = (const float4*)(s + sb);
        float4* dst = (float4*)ss;
        for (int i = l; i < SS_N / 4; i += 32) dst[i] = src[i];
    }
    __syncwarp();

    // ---- FIR: x[r] = sum_m q[m] * ss[r+m], 18 taps ----
    float q[18];
    q[0] = w_ar[0];
#pragma unroll
    for (int m = 1; m < 16; ++m) q[m] = w_ar[m] - w_ar[m - 1];
    q[16] = -1.f - w_ar[15];
    q[17] = 1.f;

    for (int e = 0; e < 17; ++e) {
        const int R = 4 * l + 128 * e;    // 4 outputs per lane per pass
        float w[24];
        const float4* sp = (const float4*)(ss + R);
#pragma unroll
        for (int v = 0; v < 6; ++v) {
            float4 t4 = sp[v];
            w[4 * v] = t4.x; w[4 * v + 1] = t4.y;
            w[4 * v + 2] = t4.z; w[4 * v + 3] = t4.w;
        }
        const int fb = R + (R >> 6);      // padded index, quad never splits
#pragma unroll
        for (int p = 0; p < 4; ++p) {
            float a = 0.f;
#pragma unroll
            for (int m = 0; m < 18; ++m) a = fmaf(q[m], w[p + m], a);
            if (g == 0 && (T0 + R + p) <= 16)        // pred suppressed: x = y
                a = w[p + 17] - w[p + 16];
            xt[fb + p] = a;
        }
    }
    __syncwarp();

    // ---- IIR: err = x + d[0]; d[j] = nc[j]*err + d[j+1] (transposed DF2) ----
    float nc[16];
#pragma unroll
    for (int j = 0; j < 16; ++j) nc[j] = -w_ma[15 - j];
    float d[16];
#pragma unroll
    for (int j = 0; j < 16; ++j) d[j] = 0.f;
    float acc = 0.f;

    int idx = 65 * l;                     // padded f(64*l)

    if (g == 0) {
        int t = T0 + 64 * l;
        for (int jo = 0; jo < 3; ++jo) {
#pragma unroll 8
            for (int ji = 0; ji < 64; ++ji) {
                float x   = xt[idx + ji];
                float err = (t > 16) ? (x + d[0]) : x;
#pragma unroll
                for (int j = 0; j < 15; ++j) d[j] = fmaf(nc[j], err, d[j + 1]);
                d[15] = nc[15] * err;
                if (jo == 2) acc = fmaf(err, err, acc);
                ++t;
            }
            idx += 65;
        }
    } else {
        for (int jo = 0; jo < 2; ++jo) {  // warmup 128 steps
#pragma unroll 8
            for (int ji = 0; ji < 64; ++ji) {
                float err = xt[idx + ji] + d[0];
#pragma unroll
                for (int j = 0; j < 15; ++j) d[j] = fmaf(nc[j], err, d[j + 1]);
                d[15] = nc[15] * err;
            }
            idx += 65;
        }
#pragma unroll 8
        for (int ji = 0; ji < 64; ++ji) { // main 64 steps
            float err = xt[idx + ji] + d[0];
#pragma unroll
            for (int j = 0; j < 15; ++j) d[j] = fmaf(nc[j], err, d[j + 1]);
            d[15] = nc[15] * err;
            acc = fmaf(err, err, acc);
        }
    }

#pragma unroll
    for (int off = 16; off; off >>= 1)
        acc += __shfl_down_sync(0xffffffffu, acc, off);
    if (l == 0) g_partial[g] = acc;
}

// ---- finish: reduce 512 partials in double, write mean ----
__global__ void finish_kernel(float* __restrict__ out) {
    __shared__ double sm[16];
    const int t = threadIdx.x;
    double v = (double)g_partial[t];
#pragma unroll
    for (int off = 16; off; off >>= 1)
        v += __shfl_down_sync(0xffffffffu, v, off);
    if ((t & 31) == 0) sm[t >> 5] = v;
    __syncthreads();
    if (t < 32) {
        double w = (t < 16) ? sm[t] : 0.0;
#pragma unroll
        for (int off = 8; off; off >>= 1)
            w += __shfl_down_sync(0xffffffffu, w, off);
        if (t == 0) out[0] = (float)(w * (1.0 / (double)S_LEN));
    }
}

extern "C" void kernel_launch(void* const* d_in, const int* in_sizes, int n_in,
                              void* d_out, int out_size) {
    const float* series = (const float*)d_in[0];
    const float* w_ar   = (const float*)d_in[1];
    const float* w_ma   = (const float*)d_in[2];
    float* out = (float*)d_out;

    fused_kernel<<<NWARP, 32>>>(series, w_ar, w_ma);
    finish_kernel<<<1, NWARP>>>(out);
}